// round 13
// baseline (speedup 1.0000x reference)
#include <cuda_runtime.h>
#include <cstdint>

// message_pass: out = prelu(prelu([x_i|x_j|ea] @ W1 + b1, a) @ W2 + b2, a)
// E*H=500000 rows, d_in=144, HID=128, C=64. fp32 I/O, TF32 mma.sync.
// 512 threads (16 warps), MT=128 rows/tile, persistent CTAs.
// k-slot permutation: mma slot t <-> logical k 2t, slot t+4 <-> 2t+1 (A and B
// packed consistently) -> LDG.64 A loads, float4 fragment-packed H.

#define OFF_W1F 0                          // 73728 B : W1 pair-packed fragments
#define OFF_W2F 73728                      // 32768 B : W2 pair-packed fragments
#define OFF_H   106496                     // 65536 B : H fragment-packed float4
#define OFF_B1  (OFF_H + 65536)            // 172032
#define OFF_B2  (OFF_B1 + 512)
#define SMEM_BYTES (OFF_B2 + 256)          // 172800 B

__device__ __forceinline__ uint32_t f2tf32(float x) {
    uint32_t r;
    asm("cvt.rna.tf32.f32 %0, %1;" : "=r"(r) : "f"(x));
    return r;
}

__device__ __forceinline__ void mma_tf32(float* d, const uint32_t* a,
                                         uint32_t b0, uint32_t b1) {
    asm volatile(
        "mma.sync.aligned.m16n8k8.row.col.f32.tf32.tf32.f32 "
        "{%0,%1,%2,%3}, {%4,%5,%6,%7}, {%8,%9}, {%0,%1,%2,%3};"
        : "+f"(d[0]), "+f"(d[1]), "+f"(d[2]), "+f"(d[3])
        : "r"(a[0]), "r"(a[1]), "r"(a[2]), "r"(a[3]), "r"(b0), "r"(b1));
}

// A fragments for k-step s: 4 rows (base+0,8,16,24), 2 consecutive k each
__device__ __forceinline__ void loadA(float2* pf,
                                      const float* __restrict__ xi,
                                      const float* __restrict__ xj,
                                      const float* __restrict__ ea,
                                      const int* rr, int s, int t2) {
    #pragma unroll
    for (int j = 0; j < 4; ++j) {
        const float* p;
        if (s < 8)       p = xi + (size_t)rr[j] * 64 + 8 * s       + t2;
        else if (s < 16) p = xj + (size_t)rr[j] * 64 + 8 * s - 64  + t2;
        else             p = ea + (size_t)rr[j] * 16 + 8 * s - 128 + t2;
        pf[j] = *(const float2*)p;
    }
}

__global__ __launch_bounds__(512, 1)
void message_pass_22548578304895_kernel(
    const float* __restrict__ xi, const float* __restrict__ xj,
    const float* __restrict__ ea, const float* __restrict__ W1g,
    const float* __restrict__ b1g, const float* __restrict__ W2g,
    const float* __restrict__ b2g, const float* __restrict__ alphap,
    float* __restrict__ out, int nrows, int ntiles)
{
    extern __shared__ char smem[];
    float* smf = (float*)smem;
    const int tid  = threadIdx.x;
    const int w    = tid >> 5;
    const int lane = tid & 31;
    const int g    = lane >> 2;
    const int t    = lane & 3;
    const int t2   = 2 * t;
    const int r1 = w >> 2, c1 = w & 3;     // layer1: 4 row-slabs(32) x 4 col-quarters(32)
    const int r2 = w & 3,  c2 = w >> 2;    // layer2: 4 row-slabs(32) x 4 col-sixteenths(16)
    const float alpha = __ldg(alphap);

    // ---- pack W1 fragments: pair p = s*8+pp covers cols 16pp..16pp+15;
    //      lane(lt,lg): {b0,b1} x {atom 2pp, 2pp+1}; b0=W[8s+2lt][col], b1=W[8s+2lt+1][col]
    for (int idx = tid; idx < 4608; idx += 512) {
        int pg_ = idx >> 5;
        int s = pg_ >> 3, pp = pg_ & 7;
        int ll = idx & 31, lt = ll & 3, lg = ll >> 2;
        int row0 = 8 * s + 2 * lt, col0 = 16 * pp + lg;
        uint4 v;
        v.x = f2tf32(W1g[row0 * 128 + col0]);
        v.y = f2tf32(W1g[(row0 + 1) * 128 + col0]);
        v.z = f2tf32(W1g[row0 * 128 + col0 + 8]);
        v.w = f2tf32(W1g[(row0 + 1) * 128 + col0 + 8]);
        *(uint4*)(smem + OFF_W1F + idx * 16) = v;
    }
    for (int idx = tid; idx < 2048; idx += 512) {
        int pg_ = idx >> 5;
        int s = pg_ >> 2, pp = pg_ & 3;
        int ll = idx & 31, lt = ll & 3, lg = ll >> 2;
        int row0 = 8 * s + 2 * lt, col0 = 16 * pp + lg;
        uint4 v;
        v.x = f2tf32(W2g[row0 * 64 + col0]);
        v.y = f2tf32(W2g[(row0 + 1) * 64 + col0]);
        v.z = f2tf32(W2g[row0 * 64 + col0 + 8]);
        v.w = f2tf32(W2g[(row0 + 1) * 64 + col0 + 8]);
        *(uint4*)(smem + OFF_W2F + idx * 16) = v;
    }
    if (tid < 128) smf[OFF_B1 / 4 + tid] = b1g[tid];
    if (tid < 64)  smf[OFF_B2 / 4 + tid] = b2g[tid];
    __syncthreads();

    int rr[4];
    float2 pf[3][4];

    // prologue prefetch (depth 3) for first tile
    {
        int tl = ((int)blockIdx.x < ntiles) ? (int)blockIdx.x : 0;
        int base = tl * 128 + r1 * 32 + g;
        #pragma unroll
        for (int j = 0; j < 4; ++j) {
            int r = base + 8 * j;
            rr[j] = (r < nrows) ? r : (nrows - 1);
        }
        loadA(pf[0], xi, xj, ea, rr, 0, t2);
        loadA(pf[1], xi, xj, ea, rr, 1, t2);
        loadA(pf[2], xi, xj, ea, rr, 2, t2);
    }

    for (int tile = blockIdx.x; tile < ntiles; tile += gridDim.x) {
        // ================= layer 1: [128,144] @ [144,128] =================
        float acc1[2][4][4];
        #pragma unroll
        for (int f = 0; f < 2; ++f)
            #pragma unroll
            for (int a4 = 0; a4 < 4; ++a4)
                #pragma unroll
                for (int r = 0; r < 4; ++r) acc1[f][a4][r] = 0.f;

        #pragma unroll
        for (int s = 0; s < 18; ++s) {
            int sl = s % 3;
            uint32_t a[2][4];
            #pragma unroll
            for (int f = 0; f < 2; ++f) {
                a[f][0] = f2tf32(pf[sl][2 * f].x);       // row g      k 2t
                a[f][2] = f2tf32(pf[sl][2 * f].y);       // row g      k 2t+1
                a[f][1] = f2tf32(pf[sl][2 * f + 1].x);   // row g+8    k 2t
                a[f][3] = f2tf32(pf[sl][2 * f + 1].y);
            }
            if (s + 3 < 18) loadA(pf[sl], xi, xj, ea, rr, s + 3, t2);
            #pragma unroll
            for (int ap = 0; ap < 2; ++ap) {
                uint4 B = *(const uint4*)(smem + OFF_W1F
                          + ((s * 8 + c1 * 2 + ap) * 32 + lane) * 16);
                mma_tf32(acc1[0][2 * ap],     a[0], B.x, B.y);
                mma_tf32(acc1[0][2 * ap + 1], a[0], B.z, B.w);
                mma_tf32(acc1[1][2 * ap],     a[1], B.x, B.y);
                mma_tf32(acc1[1][2 * ap + 1], a[1], B.z, B.w);
            }
        }

        // ---- epilogue 1: bias + prelu + rna(tf32) -> H (fragment-packed float4) ----
        // quad(s',t,m,g) = {v(g,2t), v(g+8,2t), v(g,2t+1), v(g+8,2t+1)}, s' = 4c1+at, m = 2r1+f
        #pragma unroll
        for (int f = 0; f < 2; ++f) {
            #pragma unroll
            for (int at = 0; at < 4; ++at) {
                int col = c1 * 32 + at * 8 + t2;
                float bx = smf[OFF_B1 / 4 + col], by = smf[OFF_B1 / 4 + col + 1];
                float v00 = acc1[f][at][0] + bx;   // row g,   col
                float v01 = acc1[f][at][1] + by;   // row g,   col+1
                float v10 = acc1[f][at][2] + bx;   // row g+8, col
                float v11 = acc1[f][at][3] + by;   // row g+8, col+1
                v00 = (v00 >= 0.f) ? v00 : alpha * v00;
                v01 = (v01 >= 0.f) ? v01 : alpha * v01;
                v10 = (v10 >= 0.f) ? v10 : alpha * v10;
                v11 = (v11 >= 0.f) ? v11 : alpha * v11;
                uint4 q;
                q.x = f2tf32(v00); q.y = f2tf32(v10);
                q.z = f2tf32(v01); q.w = f2tf32(v11);
                int qi = (((4 * c1 + at) * 4 + t) * 8 + (2 * r1 + f)) * 8 + g;
                *(uint4*)(smem + OFF_H + qi * 16) = q;
            }
        }
        __syncthreads();   // H complete

        // ---- cross-tile prefetch of next tile's first 3 k-steps ----
        {
            int nt = tile + gridDim.x;
            int tl = (nt < ntiles) ? nt : tile;
            int base = tl * 128 + r1 * 32 + g;
            #pragma unroll
            for (int j = 0; j < 4; ++j) {
                int r = base + 8 * j;
                rr[j] = (r < nrows) ? r : (nrows - 1);
            }
            loadA(pf[0], xi, xj, ea, rr, 0, t2);
            loadA(pf[1], xi, xj, ea, rr, 1, t2);
            loadA(pf[2], xi, xj, ea, rr, 2, t2);
        }

        // ================= layer 2: [128,128] @ [128,64] =================
        float acc2[2][2][4];
        #pragma unroll
        for (int f = 0; f < 2; ++f)
            #pragma unroll
            for (int a2_ = 0; a2_ < 2; ++a2_)
                #pragma unroll
                for (int r = 0; r < 4; ++r) acc2[f][a2_][r] = 0.f;

        #pragma unroll
        for (int s = 0; s < 16; ++s) {
            uint4 B = *(const uint4*)(smem + OFF_W2F
                      + ((s * 4 + c2) * 32 + lane) * 16);
            #pragma unroll
            for (int f = 0; f < 2; ++f) {
                int qi = ((s * 4 + t) * 8 + (2 * r2 + f)) * 8 + g;
                uint4 q = *(const uint4*)(smem + OFF_H + qi * 16);
                uint32_t a[4] = {q.x, q.y, q.z, q.w};
                mma_tf32(acc2[f][0], a, B.x, B.y);
                mma_tf32(acc2[f][1], a, B.z, B.w);
            }
        }
        __syncthreads();   // H reads done; next epi1 may overwrite

        // ---- epilogue 2: bias + prelu -> gmem (float2, full 32B sectors) ----
        #pragma unroll
        for (int f = 0; f < 2; ++f) {
            #pragma unroll
            for (int at = 0; at < 2; ++at) {
                int col = c2 * 16 + at * 8 + t2;
                float bx = smf[OFF_B2 / 4 + col], by = smf[OFF_B2 / 4 + col + 1];
                #pragma unroll
                for (int pr = 0; pr < 2; ++pr) {
                    int row  = r2 * 32 + f * 16 + g + pr * 8;
                    int grow = tile * 128 + row;
                    float v0 = acc2[f][at][2 * pr]     + bx;
                    float v1 = acc2[f][at][2 * pr + 1] + by;
                    v0 = (v0 >= 0.f) ? v0 : alpha * v0;
                    v1 = (v1 >= 0.f) ? v1 : alpha * v1;
                    if (grow < nrows)
                        *(float2*)(out + (size_t)grow * 64 + col) = make_float2(v0, v1);
                }
            }
        }
    }
}

extern "C" void kernel_launch(void* const* d_in, const int* in_sizes, int n_in,
                              void* d_out, int out_size) {
    const float* xi     = (const float*)d_in[0];
    const float* xj     = (const float*)d_in[1];
    const float* ea     = (const float*)d_in[2];
    const float* W1     = (const float*)d_in[3];
    const float* b1     = (const float*)d_in[4];
    const float* W2     = (const float*)d_in[5];
    const float* b2     = (const float*)d_in[6];
    const float* alphap = (const float*)d_in[7];
    float* out = (float*)d_out;

    int nrows  = in_sizes[0] / 64;                 // E*H
    int ntiles = (nrows + 127) / 128;

    int dev = 0, sms = 148;
    cudaGetDevice(&dev);
    cudaDeviceGetAttribute(&sms, cudaDevAttrMultiProcessorCount, dev);

    cudaFuncSetAttribute(message_pass_22548578304895_kernel,
                         cudaFuncAttributeMaxDynamicSharedMemorySize, SMEM_BYTES);

    int grid = sms < ntiles ? sms : ntiles;
    message_pass_22548578304895_kernel<<<grid, 512, SMEM_BYTES>>>(
        xi, xj, ea, W1, b1, W2, b2, alphap, out, nrows, ntiles);
}

// round 14
// speedup vs baseline: 1.7329x; 1.7329x over previous
#include <cuda_runtime.h>
#include <cstdint>

// message_pass: out = prelu(prelu([x_i|x_j|ea] @ W1 + b1, a) @ W2 + b2, a)
// E*H=500000 rows, d_in=144, HID=128, C=64. fp32 I/O, TF32 mma.sync.
// 256 threads / 8 warps; warp w owns rows 16w..16w+15 of a 128-row tile and
// computes ALL columns of both layers; layer-1 accumulators are reused
// directly as layer-2 A fragments (k-slot permutation) -> H never hits SMEM.

#define XSTR 152                          // staging row stride: mod-32 = 24 -> conflict-free LDS.64
#define OFF_W1F 0                         // 73728 B : W1 pair-packed fragments
#define OFF_W2F 73728                     // 32768 B : W2 pair-packed fragments
#define OFF_STG 106496                    // 3 x 64-row staging buffers
#define STG_BY  (64*XSTR*4)               // 38912 B each
#define OFF_B1  (OFF_STG + 3*STG_BY)      // 223232
#define OFF_B2  (OFF_B1 + 512)            // 223744
#define SMEM_BYTES (OFF_B2 + 256)         // 224000 B

__device__ __forceinline__ uint32_t f2tf32(float x) {
    uint32_t r;
    asm("cvt.rna.tf32.f32 %0, %1;" : "=r"(r) : "f"(x));
    return r;
}

__device__ __forceinline__ void mma_tf32(float* d, const uint32_t* a,
                                         uint32_t b0, uint32_t b1) {
    asm volatile(
        "mma.sync.aligned.m16n8k8.row.col.f32.tf32.tf32.f32 "
        "{%0,%1,%2,%3}, {%4,%5,%6,%7}, {%8,%9}, {%0,%1,%2,%3};"
        : "+f"(d[0]), "+f"(d[1]), "+f"(d[2]), "+f"(d[3])
        : "r"(a[0]), "r"(a[1]), "r"(a[2]), "r"(a[3]), "r"(b0), "r"(b1));
}

__device__ __forceinline__ void cp_async16(float* smem_dst, const float* gsrc, int src_bytes) {
    uint32_t sa = (uint32_t)__cvta_generic_to_shared(smem_dst);
    asm volatile("cp.async.cg.shared.global [%0], [%1], 16, %2;"
                 :: "r"(sa), "l"(gsrc), "r"(src_bytes));
}
#define CP_COMMIT() asm volatile("cp.async.commit_group;" ::: "memory")
#define CP_WAIT(n)  asm volatile("cp.async.wait_group %0;" :: "n"(n) : "memory")

// stage 64 rows (grow0..grow0+63) of [x_i|x_j|ea] into dst (stride XSTR)
__device__ __forceinline__ void stage_half(
    float* dst, const float* __restrict__ xi, const float* __restrict__ xj,
    const float* __restrict__ ea, int grow0, int tid, int nrows)
{
    #pragma unroll
    for (int j = 0; j < 9; ++j) {
        int v   = tid + 256 * j;          // 2304 = 64 rows * 36 float4
        int row = v / 36;
        int col = (v % 36) * 4;
        int grow = grow0 + row;
        int nb   = (grow < nrows) ? 16 : 0;
        int gr   = (grow < nrows) ? grow : (nrows - 1);
        const float* src;
        if (col < 64)        src = xi + (size_t)gr * 64 + col;
        else if (col < 128)  src = xj + (size_t)gr * 64 + (col - 64);
        else                 src = ea + (size_t)gr * 16 + (col - 128);
        cp_async16(dst + row * XSTR + col, src, nb);
    }
}

__global__ __launch_bounds__(256, 1)
void message_pass_22548578304895_kernel(
    const float* __restrict__ xi, const float* __restrict__ xj,
    const float* __restrict__ ea, const float* __restrict__ W1g,
    const float* __restrict__ b1g, const float* __restrict__ W2g,
    const float* __restrict__ b2g, const float* __restrict__ alphap,
    float* __restrict__ out, int nrows, int ntiles)
{
    extern __shared__ char smem[];
    float* smf = (float*)smem;
    const int tid  = threadIdx.x;
    const int w    = tid >> 5;
    const int lane = tid & 31;
    const int g    = lane >> 2;
    const int t    = lane & 3;
    const int t2   = 2 * t;
    const float alpha = __ldg(alphap);

    // ---- pack W1 fragments: pair p = s*8+pp covers cols 16pp..16pp+15;
    //      lane(lt,lg): b0=W[8s+2lt][col], b1=W[8s+2lt+1][col]; {.x,.y}=atom 2pp, {.z,.w}=atom 2pp+1
    for (int idx = tid; idx < 4608; idx += 256) {
        int pg_ = idx >> 5;
        int s = pg_ >> 3, pp = pg_ & 7;
        int ll = idx & 31, lt = ll & 3, lg = ll >> 2;
        int row0 = 8 * s + 2 * lt, col0 = 16 * pp + lg;
        uint4 v;
        v.x = f2tf32(W1g[row0 * 128 + col0]);
        v.y = f2tf32(W1g[(row0 + 1) * 128 + col0]);
        v.z = f2tf32(W1g[row0 * 128 + col0 + 8]);
        v.w = f2tf32(W1g[(row0 + 1) * 128 + col0 + 8]);
        *(uint4*)(smem + OFF_W1F + idx * 16) = v;
    }
    for (int idx = tid; idx < 2048; idx += 256) {
        int pg_ = idx >> 5;
        int s = pg_ >> 2, pp = pg_ & 3;
        int ll = idx & 31, lt = ll & 3, lg = ll >> 2;
        int row0 = 8 * s + 2 * lt, col0 = 16 * pp + lg;
        uint4 v;
        v.x = f2tf32(W2g[row0 * 64 + col0]);
        v.y = f2tf32(W2g[(row0 + 1) * 64 + col0]);
        v.z = f2tf32(W2g[row0 * 64 + col0 + 8]);
        v.w = f2tf32(W2g[(row0 + 1) * 64 + col0 + 8]);
        *(uint4*)(smem + OFF_W2F + idx * 16) = v;
    }
    if (tid < 128) smf[OFF_B1 / 4 + tid] = b1g[tid];
    if (tid < 64)  smf[OFF_B2 / 4 + tid] = b2g[tid];
    __syncthreads();

    float* stg = smf + OFF_STG / 4;
    const int t0 = blockIdx.x, gstep = gridDim.x;

    // prologue: t0.h0 -> buf0, t0.h1 -> buf1, (t0+g).h0 -> buf2
    stage_half(stg + 0 * (STG_BY / 4), xi, xj, ea, t0 * 128,            tid, nrows); CP_COMMIT();
    stage_half(stg + 1 * (STG_BY / 4), xi, xj, ea, t0 * 128 + 64,       tid, nrows); CP_COMMIT();
    stage_half(stg + 2 * (STG_BY / 4), xi, xj, ea, (t0 + gstep) * 128,  tid, nrows); CP_COMMIT();

    int p = 0;                 // buffer rotation: tile's h0 = buf p, h1 = buf (p+1)%3

    for (int tile = t0; tile < ntiles; tile += gstep) {
        CP_WAIT(1);            // both halves of this tile arrived
        __syncthreads();

        // warp's 16-row slab: warps 0-3 in h0, 4-7 in h1
        const float* Xw = stg + ((w < 4) ? p : ((p + 1) % 3)) * (STG_BY / 4)
                        + ((w & 3) * 16 + g) * XSTR;

        // ================= layer 1: 16 rows x 128 cols per warp =================
        float acc1[16][4];
        #pragma unroll
        for (int at = 0; at < 16; ++at)
            #pragma unroll
            for (int r = 0; r < 4; ++r) acc1[at][r] = 0.f;

        #pragma unroll
        for (int s = 0; s < 18; ++s) {
            float2 lo = *(const float2*)(Xw + 8 * s + t2);               // row g
            float2 hi = *(const float2*)(Xw + 8 * XSTR + 8 * s + t2);    // row g+8
            uint32_t a[4];
            a[0] = f2tf32(lo.x);   // slot t   : k 8s+2t,   row g
            a[2] = f2tf32(lo.y);   // slot t+4 : k 8s+2t+1, row g
            a[1] = f2tf32(hi.x);   //                       row g+8
            a[3] = f2tf32(hi.y);
            #pragma unroll
            for (int pp = 0; pp < 8; ++pp) {
                uint4 B = *(const uint4*)(smem + OFF_W1F + ((s * 8 + pp) * 32 + lane) * 16);
                mma_tf32(acc1[2 * pp],     a, B.x, B.y);
                mma_tf32(acc1[2 * pp + 1], a, B.z, B.w);
            }
        }

        // ---- bias + prelu + rna(tf32) in place: acc1 becomes H fragments ----
        #pragma unroll
        for (int at = 0; at < 16; ++at) {
            float2 b = *(const float2*)(smf + OFF_B1 / 4 + 8 * at + t2);
            float v0 = acc1[at][0] + b.x;   // row g,   col 8at+2t
            float v1 = acc1[at][1] + b.y;   // row g,   col 8at+2t+1
            float v2 = acc1[at][2] + b.x;   // row g+8, col 8at+2t
            float v3 = acc1[at][3] + b.y;
            v0 = (v0 >= 0.f) ? v0 : alpha * v0;
            v1 = (v1 >= 0.f) ? v1 : alpha * v1;
            v2 = (v2 >= 0.f) ? v2 : alpha * v2;
            v3 = (v3 >= 0.f) ? v3 : alpha * v3;
            acc1[at][0] = __uint_as_float(f2tf32(v0));
            acc1[at][1] = __uint_as_float(f2tf32(v1));
            acc1[at][2] = __uint_as_float(f2tf32(v2));
            acc1[at][3] = __uint_as_float(f2tf32(v3));
        }
        __syncthreads();       // all X reads of this tile complete

        // ---- prefetch next halves into freed buffers (overlaps layer 2) ----
        stage_half(stg + p * (STG_BY / 4),             xi, xj, ea,
                   (tile + gstep) * 128 + 64, tid, nrows); CP_COMMIT();
        stage_half(stg + ((p + 1) % 3) * (STG_BY / 4), xi, xj, ea,
                   (tile + 2 * gstep) * 128, tid, nrows);  CP_COMMIT();

        // ================= layer 2: H(regs) @ W2 -> 16 rows x 64 cols =================
        float acc2[8][4];
        #pragma unroll
        for (int at = 0; at < 8; ++at)
            #pragma unroll
            for (int r = 0; r < 4; ++r) acc2[at][r] = 0.f;

        #pragma unroll
        for (int s = 0; s < 16; ++s) {
            // k-slot permutation: a = {d0, d2, d1, d3} of acc1[s]
            uint32_t a[4];
            a[0] = __float_as_uint(acc1[s][0]);
            a[1] = __float_as_uint(acc1[s][2]);
            a[2] = __float_as_uint(acc1[s][1]);
            a[3] = __float_as_uint(acc1[s][3]);
            #pragma unroll
            for (int pp = 0; pp < 4; ++pp) {
                uint4 B = *(const uint4*)(smem + OFF_W2F + ((s * 4 + pp) * 32 + lane) * 16);
                mma_tf32(acc2[2 * pp],     a, B.x, B.y);
                mma_tf32(acc2[2 * pp + 1], a, B.z, B.w);
            }
        }

        // ---- epilogue 2: bias + prelu -> gmem ----
        int rowbase = tile * 128 + (w << 4) + g;
        #pragma unroll
        for (int at = 0; at < 8; ++at) {
            int col = 8 * at + t2;
            float2 b = *(const float2*)(smf + OFF_B2 / 4 + col);
            float v0 = acc2[at][0] + b.x;
            float v1 = acc2[at][1] + b.y;
            float v2 = acc2[at][2] + b.x;
            float v3 = acc2[at][3] + b.y;
            v0 = (v0 >= 0.f) ? v0 : alpha * v0;
            v1 = (v1 >= 0.f) ? v1 : alpha * v1;
            v2 = (v2 >= 0.f) ? v2 : alpha * v2;
            v3 = (v3 >= 0.f) ? v3 : alpha * v3;
            if (rowbase < nrows)
                *(float2*)(out + (size_t)rowbase * 64 + col) = make_float2(v0, v1);
            if (rowbase + 8 < nrows)
                *(float2*)(out + (size_t)(rowbase + 8) * 64 + col) = make_float2(v2, v3);
        }

        p = (p + 2) % 3;
    }
}

extern "C" void kernel_launch(void* const* d_in, const int* in_sizes, int n_in,
                              void* d_out, int out_size) {
    const float* xi     = (const float*)d_in[0];
    const float* xj     = (const float*)d_in[1];
    const float* ea     = (const float*)d_in[2];
    const float* W1     = (const float*)d_in[3];
    const float* b1     = (const float*)d_in[4];
    const float* W2     = (const float*)d_in[5];
    const float* b2     = (const float*)d_in[6];
    const float* alphap = (const float*)d_in[7];
    float* out = (float*)d_out;

    int nrows  = in_sizes[0] / 64;                 // E*H
    int ntiles = (nrows + 127) / 128;

    int dev = 0, sms = 148;
    cudaGetDevice(&dev);
    cudaDeviceGetAttribute(&sms, cudaDevAttrMultiProcessorCount, dev);

    cudaFuncSetAttribute(message_pass_22548578304895_kernel,
                         cudaFuncAttributeMaxDynamicSharedMemorySize, SMEM_BYTES);

    int grid = sms < ntiles ? sms : ntiles;
    message_pass_22548578304895_kernel<<<grid, 256, SMEM_BYTES>>>(
        xi, xj, ea, W1, b1, W2, b2, alphap, out, nrows, ntiles);
}

// round 15
// speedup vs baseline: 2.6253x; 1.5150x over previous
#include <cuda_runtime.h>
#include <cuda_fp16.h>
#include <cstdint>

// message_pass: out = prelu(prelu([x_i|x_j|ea] @ W1 + b1, a) @ W2 + b2, a)
// E*H=500000 rows, d_in=144, HID=128, C=64. fp32 I/O, FP16 mma (m16n8k16, fp32 acc).
// 256 threads / 8 warps; warp w owns rows 16w..16w+15 of a 128-row tile and
// computes ALL columns of both layers; layer-1 accumulators convert in-register
// to layer-2 A fragments (standard m16n8k16 layouts, no permutation). H never
// touches SMEM.

#define XSTR 152                          // staging row stride (floats): conflict-free LDS.64
#define OFF_W1F 0                         // 36864 B : W1 pair-packed fragments (9 steps x 8 pairs)
#define OFF_W2F 36864                     // 16384 B : W2 pair-packed fragments (8 steps x 4 pairs)
#define OFF_STG 53248                     // 3 x 64-row staging buffers
#define STG_BY  (64*XSTR*4)               // 38912 B each
#define OFF_B1  (OFF_STG + 3*STG_BY)      // 169984
#define OFF_B2  (OFF_B1 + 512)            // 170496
#define SMEM_BYTES (OFF_B2 + 256)         // 170752 B

__device__ __forceinline__ uint32_t pack_h2(float lo, float hi) {
    __half2 h = __floats2half2_rn(lo, hi);
    return *reinterpret_cast<uint32_t*>(&h);
}

__device__ __forceinline__ void mma_f16(float* d, const uint32_t* a,
                                        uint32_t b0, uint32_t b1) {
    asm volatile(
        "mma.sync.aligned.m16n8k16.row.col.f32.f16.f16.f32 "
        "{%0,%1,%2,%3}, {%4,%5,%6,%7}, {%8,%9}, {%0,%1,%2,%3};"
        : "+f"(d[0]), "+f"(d[1]), "+f"(d[2]), "+f"(d[3])
        : "r"(a[0]), "r"(a[1]), "r"(a[2]), "r"(a[3]), "r"(b0), "r"(b1));
}

__device__ __forceinline__ void cp_async16(float* smem_dst, const float* gsrc, int src_bytes) {
    uint32_t sa = (uint32_t)__cvta_generic_to_shared(smem_dst);
    asm volatile("cp.async.cg.shared.global [%0], [%1], 16, %2;"
                 :: "r"(sa), "l"(gsrc), "r"(src_bytes));
}
#define CP_COMMIT() asm volatile("cp.async.commit_group;" ::: "memory")
#define CP_WAIT(n)  asm volatile("cp.async.wait_group %0;" :: "n"(n) : "memory")

// stage 64 rows (grow0..grow0+63) of [x_i|x_j|ea] into dst (stride XSTR)
__device__ __forceinline__ void stage_half(
    float* dst, const float* __restrict__ xi, const float* __restrict__ xj,
    const float* __restrict__ ea, int grow0, int tid, int nrows)
{
    #pragma unroll
    for (int j = 0; j < 9; ++j) {
        int v   = tid + 256 * j;          // 2304 = 64 rows * 36 float4
        int row = v / 36;
        int col = (v % 36) * 4;
        int grow = grow0 + row;
        int nb   = (grow < nrows) ? 16 : 0;
        int gr   = (grow < nrows) ? grow : (nrows - 1);
        const float* src;
        if (col < 64)        src = xi + (size_t)gr * 64 + col;
        else if (col < 128)  src = xj + (size_t)gr * 64 + (col - 64);
        else                 src = ea + (size_t)gr * 16 + (col - 128);
        cp_async16(dst + row * XSTR + col, src, nb);
    }
}

__global__ __launch_bounds__(256, 1)
void message_pass_22548578304895_kernel(
    const float* __restrict__ xi, const float* __restrict__ xj,
    const float* __restrict__ ea, const float* __restrict__ W1g,
    const float* __restrict__ b1g, const float* __restrict__ W2g,
    const float* __restrict__ b2g, const float* __restrict__ alphap,
    float* __restrict__ out, int nrows, int ntiles)
{
    extern __shared__ char smem[];
    float* smf = (float*)smem;
    const int tid  = threadIdx.x;
    const int w    = tid >> 5;
    const int lane = tid & 31;
    const int g    = lane >> 2;
    const int t    = lane & 3;
    const int t2   = 2 * t;
    const float alpha = __ldg(alphap);

    // ---- pack W1 fragments (m16n8k16 B layout, col-pairs):
    //      entry (s,pp): lane(lt,lg):
    //      .x = h2(W[16s+2lt][c0],   W[16s+2lt+1][c0])    b0, block 2pp
    //      .y = h2(W[16s+2lt+8][c0], W[16s+2lt+9][c0])    b1, block 2pp
    //      .z,.w = same for c1 = c0+8 (block 2pp+1);  c0 = 16pp+lg
    for (int idx = tid; idx < 2304; idx += 256) {
        int pg_ = idx >> 5;
        int s = pg_ >> 3, pp = pg_ & 7;
        int ll = idx & 31, lt = ll & 3, lg = ll >> 2;
        int r0 = 16 * s + 2 * lt;
        int c0 = 16 * pp + lg;
        uint4 v;
        v.x = pack_h2(W1g[r0 * 128 + c0],       W1g[(r0 + 1) * 128 + c0]);
        v.y = pack_h2(W1g[(r0 + 8) * 128 + c0], W1g[(r0 + 9) * 128 + c0]);
        v.z = pack_h2(W1g[r0 * 128 + c0 + 8],       W1g[(r0 + 1) * 128 + c0 + 8]);
        v.w = pack_h2(W1g[(r0 + 8) * 128 + c0 + 8], W1g[(r0 + 9) * 128 + c0 + 8]);
        *(uint4*)(smem + OFF_W1F + idx * 16) = v;
    }
    for (int idx = tid; idx < 1024; idx += 256) {
        int pg_ = idx >> 5;
        int s = pg_ >> 2, pp = pg_ & 3;
        int ll = idx & 31, lt = ll & 3, lg = ll >> 2;
        int r0 = 16 * s + 2 * lt;
        int c0 = 16 * pp + lg;
        uint4 v;
        v.x = pack_h2(W2g[r0 * 64 + c0],       W2g[(r0 + 1) * 64 + c0]);
        v.y = pack_h2(W2g[(r0 + 8) * 64 + c0], W2g[(r0 + 9) * 64 + c0]);
        v.z = pack_h2(W2g[r0 * 64 + c0 + 8],       W2g[(r0 + 1) * 64 + c0 + 8]);
        v.w = pack_h2(W2g[(r0 + 8) * 64 + c0 + 8], W2g[(r0 + 9) * 64 + c0 + 8]);
        *(uint4*)(smem + OFF_W2F + idx * 16) = v;
    }
    if (tid < 128) smf[OFF_B1 / 4 + tid] = b1g[tid];
    if (tid < 64)  smf[OFF_B2 / 4 + tid] = b2g[tid];
    __syncthreads();

    float* stg = smf + OFF_STG / 4;
    const int t0 = blockIdx.x, gstep = gridDim.x;

    // prologue: t0.h0 -> buf0, t0.h1 -> buf1, (t0+g).h0 -> buf2
    stage_half(stg + 0 * (STG_BY / 4), xi, xj, ea, t0 * 128,            tid, nrows); CP_COMMIT();
    stage_half(stg + 1 * (STG_BY / 4), xi, xj, ea, t0 * 128 + 64,       tid, nrows); CP_COMMIT();
    stage_half(stg + 2 * (STG_BY / 4), xi, xj, ea, (t0 + gstep) * 128,  tid, nrows); CP_COMMIT();

    int p = 0;                 // buffer rotation: tile's h0 = buf p, h1 = buf (p+1)%3

    for (int tile = t0; tile < ntiles; tile += gstep) {
        CP_WAIT(1);            // both halves of this tile arrived
        __syncthreads();

        // warp's 16-row slab: warps 0-3 in h0, 4-7 in h1
        const float* Xw = stg + ((w < 4) ? p : ((p + 1) % 3)) * (STG_BY / 4)
                        + ((w & 3) * 16 + g) * XSTR;

        // ================= layer 1: 16 rows x 128 cols per warp =================
        float acc1[16][4];
        #pragma unroll
        for (int at = 0; at < 16; ++at)
            #pragma unroll
            for (int r = 0; r < 4; ++r) acc1[at][r] = 0.f;

        #pragma unroll
        for (int s = 0; s < 9; ++s) {
            // A fragments (m16k16): a0=(g, k 16s+2t..), a1=(g+8, same), a2/a3 = +8 in k
            float2 l0 = *(const float2*)(Xw + 16 * s + t2);                  // row g,   k lo
            float2 l1 = *(const float2*)(Xw + 8 * XSTR + 16 * s + t2);       // row g+8, k lo
            float2 l2 = *(const float2*)(Xw + 16 * s + 8 + t2);              // row g,   k hi
            float2 l3 = *(const float2*)(Xw + 8 * XSTR + 16 * s + 8 + t2);   // row g+8, k hi
            uint32_t a[4];
            a[0] = pack_h2(l0.x, l0.y);
            a[1] = pack_h2(l1.x, l1.y);
            a[2] = pack_h2(l2.x, l2.y);
            a[3] = pack_h2(l3.x, l3.y);
            #pragma unroll
            for (int pp = 0; pp < 8; ++pp) {
                uint4 B = *(const uint4*)(smem + OFF_W1F + ((s * 8 + pp) * 32 + lane) * 16);
                mma_f16(acc1[2 * pp],     a, B.x, B.y);
                mma_f16(acc1[2 * pp + 1], a, B.z, B.w);
            }
        }

        // ---- bias + prelu -> fp16 H fragments in registers ----
        uint32_t hf[32];       // hf[2at] = h2(row g: col, col+1), hf[2at+1] = h2(row g+8: ...)
        #pragma unroll
        for (int at = 0; at < 16; ++at) {
            float2 b = *(const float2*)(smf + OFF_B1 / 4 + 8 * at + t2);
            float v0 = acc1[at][0] + b.x;   // row g,   col 8at+2t
            float v1 = acc1[at][1] + b.y;   // row g,   col 8at+2t+1
            float v2 = acc1[at][2] + b.x;   // row g+8, col 8at+2t
            float v3 = acc1[at][3] + b.y;
            v0 = (v0 >= 0.f) ? v0 : alpha * v0;
            v1 = (v1 >= 0.f) ? v1 : alpha * v1;
            v2 = (v2 >= 0.f) ? v2 : alpha * v2;
            v3 = (v3 >= 0.f) ? v3 : alpha * v3;
            hf[2 * at]     = pack_h2(v0, v1);
            hf[2 * at + 1] = pack_h2(v2, v3);
        }
        __syncthreads();       // all X reads of this tile complete

        // ---- prefetch next halves into freed buffers (overlaps layer 2) ----
        stage_half(stg + p * (STG_BY / 4),             xi, xj, ea,
                   (tile + gstep) * 128 + 64, tid, nrows); CP_COMMIT();
        stage_half(stg + ((p + 1) % 3) * (STG_BY / 4), xi, xj, ea,
                   (tile + 2 * gstep) * 128, tid, nrows);  CP_COMMIT();

        // ================= layer 2: H(regs) @ W2 -> 16 rows x 64 cols =================
        float acc2[8][4];
        #pragma unroll
        for (int at = 0; at < 8; ++at)
            #pragma unroll
            for (int r = 0; r < 4; ++r) acc2[at][r] = 0.f;

        #pragma unroll
        for (int s = 0; s < 8; ++s) {
            // k-step s covers H cols 16s..16s+15 = D blocks 2s (lo k8) and 2s+1 (hi k8)
            uint32_t a[4];
            a[0] = hf[4 * s];       // row g,   k 16s+2t,2t+1
            a[1] = hf[4 * s + 1];   // row g+8, k 16s+2t,2t+1
            a[2] = hf[4 * s + 2];   // row g,   k 16s+8+2t,2t+1
            a[3] = hf[4 * s + 3];   // row g+8, k 16s+8+2t,2t+1
            #pragma unroll
            for (int pp = 0; pp < 4; ++pp) {
                uint4 B = *(const uint4*)(smem + OFF_W2F + ((s * 4 + pp) * 32 + lane) * 16);
                mma_f16(acc2[2 * pp],     a, B.x, B.y);
                mma_f16(acc2[2 * pp + 1], a, B.z, B.w);
            }
        }

        // ---- epilogue 2: bias + prelu -> gmem ----
        int rowbase = tile * 128 + (w << 4) + g;
        #pragma unroll
        for (int at = 0; at < 8; ++at) {
            int col = 8 * at + t2;
            float2 b = *(const float2*)(smf + OFF_B2 / 4 + col);
            float v0 = acc2[at][0] + b.x;
            float v1 = acc2[at][1] + b.y;
            float v2 = acc2[at][2] + b.x;
            float v3 = acc2[at][3] + b.y;
            v0 = (v0 >= 0.f) ? v0 : alpha * v0;
            v1 = (v1 >= 0.f) ? v1 : alpha * v1;
            v2 = (v2 >= 0.f) ? v2 : alpha * v2;
            v3 = (v3 >= 0.f) ? v3 : alpha * v3;
            if (rowbase < nrows)
                *(float2*)(out + (size_t)rowbase * 64 + col) = make_float2(v0, v1);
            if (rowbase + 8 < nrows)
                *(float2*)(out + (size_t)(rowbase + 8) * 64 + col) = make_float2(v2, v3);
        }

        p = (p + 2) % 3;
    }
}

extern "C" void kernel_launch(void* const* d_in, const int* in_sizes, int n_in,
                              void* d_out, int out_size) {
    const float* xi     = (const float*)d_in[0];
    const float* xj     = (const float*)d_in[1];
    const float* ea     = (const float*)d_in[2];
    const float* W1     = (const float*)d_in[3];
    const float* b1     = (const float*)d_in[4];
    const float* W2     = (const float*)d_in[5];
    const float* b2     = (const float*)d_in[6];
    const float* alphap = (const float*)d_in[7];
    float* out = (float*)d_out;

    int nrows  = in_sizes[0] / 64;                 // E*H
    int ntiles = (nrows + 127) / 128;

    int dev = 0, sms = 148;
    cudaGetDevice(&dev);
    cudaDeviceGetAttribute(&sms, cudaDevAttrMultiProcessorCount, dev);

    cudaFuncSetAttribute(message_pass_22548578304895_kernel,
                         cudaFuncAttributeMaxDynamicSharedMemorySize, SMEM_BYTES);

    int grid = sms < ntiles ? sms : ntiles;
    message_pass_22548578304895_kernel<<<grid, 256, SMEM_BYTES>>>(
        xi, xj, ea, W1, b1, W2, b2, alphap, out, nrows, ntiles);
}

// round 16
// speedup vs baseline: 2.7017x; 1.0291x over previous
#include <cuda_runtime.h>
#include <cuda_fp16.h>
#include <cstdint>

// message_pass: out = prelu(prelu([x_i|x_j|ea] @ W1 + b1, a) @ W2 + b2, a)
// E*H=500000 rows, d_in=144, HID=128, C=64. fp32 I/O, FP16 mma (m16n8k16, fp32 acc).
// 384 threads / 12 warps; warp w owns 16 rows of a 192-row tile, all columns of
// both layers. Layer-1 accumulators are converted in place into layer-2 A
// fragments (H never touches SMEM). X staged via cp.async into 4 rotating
// 64-row buffers.

#define XSTR 152                          // staging row stride (floats): conflict-free LDS.64
#define OFF_W1F 0                         // 36864 B : W1 pair-packed fragments (9 steps x 8 pairs)
#define OFF_W2F 36864                     // 16384 B : W2 pair-packed fragments (8 steps x 4 pairs)
#define OFF_STG 53248                     // 4 x 64-row staging buffers
#define STG_FL  (64*XSTR)                 // floats per buffer
#define STG_BY  (STG_FL*4)                // 38912 B each
#define OFF_B1  (OFF_STG + 4*STG_BY)      // 208896
#define OFF_B2  (OFF_B1 + 512)            // 209408
#define SMEM_BYTES (OFF_B2 + 256)         // 209664 B

__device__ __forceinline__ uint32_t pack_h2(float lo, float hi) {
    __half2 h = __floats2half2_rn(lo, hi);
    return *reinterpret_cast<uint32_t*>(&h);
}

__device__ __forceinline__ void mma_f16(float* d, const uint32_t* a,
                                        uint32_t b0, uint32_t b1) {
    asm volatile(
        "mma.sync.aligned.m16n8k16.row.col.f32.f16.f16.f32 "
        "{%0,%1,%2,%3}, {%4,%5,%6,%7}, {%8,%9}, {%0,%1,%2,%3};"
        : "+f"(d[0]), "+f"(d[1]), "+f"(d[2]), "+f"(d[3])
        : "r"(a[0]), "r"(a[1]), "r"(a[2]), "r"(a[3]), "r"(b0), "r"(b1));
}

__device__ __forceinline__ void cp_async16(float* smem_dst, const float* gsrc, int src_bytes) {
    uint32_t sa = (uint32_t)__cvta_generic_to_shared(smem_dst);
    asm volatile("cp.async.cg.shared.global [%0], [%1], 16, %2;"
                 :: "r"(sa), "l"(gsrc), "r"(src_bytes));
}
#define CP_COMMIT() asm volatile("cp.async.commit_group;" ::: "memory")
#define CP_WAIT(n)  asm volatile("cp.async.wait_group %0;" :: "n"(n) : "memory")

// stage 64 rows (grow0..grow0+63) of [x_i|x_j|ea] into dst (stride XSTR)
__device__ __forceinline__ void stage_half(
    float* dst, const float* __restrict__ xi, const float* __restrict__ xj,
    const float* __restrict__ ea, int grow0, int tid, int nrows)
{
    #pragma unroll
    for (int j = 0; j < 6; ++j) {
        int v   = tid + 384 * j;          // 2304 = 64 rows * 36 float4
        int row = v / 36;
        int col = (v % 36) * 4;
        int grow = grow0 + row;
        int nb   = (grow < nrows) ? 16 : 0;
        int gr   = (grow < nrows) ? grow : (nrows - 1);
        const float* src;
        if (col < 64)        src = xi + (size_t)gr * 64 + col;
        else if (col < 128)  src = xj + (size_t)gr * 64 + (col - 64);
        else                 src = ea + (size_t)gr * 16 + (col - 128);
        cp_async16(dst + row * XSTR + col, src, nb);
    }
}

__global__ __launch_bounds__(384, 1)
void message_pass_22548578304895_kernel(
    const float* __restrict__ xi, const float* __restrict__ xj,
    const float* __restrict__ ea, const float* __restrict__ W1g,
    const float* __restrict__ b1g, const float* __restrict__ W2g,
    const float* __restrict__ b2g, const float* __restrict__ alphap,
    float* __restrict__ out, int nrows, int ntiles)
{
    extern __shared__ char smem[];
    float* smf = (float*)smem;
    const int tid  = threadIdx.x;
    const int w    = tid >> 5;
    const int lane = tid & 31;
    const int g    = lane >> 2;
    const int t    = lane & 3;
    const int t2   = 2 * t;
    const float alpha = __ldg(alphap);

    // ---- pack W1 fragments (m16n8k16 B layout, col-pairs):
    //      entry (s,pp), lane(lt,lg), c0 = 16pp+lg:
    //      .x = h2(W[16s+2lt][c0],   W[16s+2lt+1][c0])   b0 of block 2pp
    //      .y = h2(W[16s+2lt+8][c0], W[16s+2lt+9][c0])   b1 of block 2pp
    //      .z/.w = same for c0+8 (block 2pp+1)
    for (int idx = tid; idx < 2304; idx += 384) {
        int pg_ = idx >> 5;
        int s = pg_ >> 3, pp = pg_ & 7;
        int ll = idx & 31, lt = ll & 3, lg = ll >> 2;
        int r0 = 16 * s + 2 * lt;
        int c0 = 16 * pp + lg;
        uint4 v;
        v.x = pack_h2(W1g[r0 * 128 + c0],       W1g[(r0 + 1) * 128 + c0]);
        v.y = pack_h2(W1g[(r0 + 8) * 128 + c0], W1g[(r0 + 9) * 128 + c0]);
        v.z = pack_h2(W1g[r0 * 128 + c0 + 8],       W1g[(r0 + 1) * 128 + c0 + 8]);
        v.w = pack_h2(W1g[(r0 + 8) * 128 + c0 + 8], W1g[(r0 + 9) * 128 + c0 + 8]);
        *(uint4*)(smem + OFF_W1F + idx * 16) = v;
    }
    for (int idx = tid; idx < 1024; idx += 384) {
        int pg_ = idx >> 5;
        int s = pg_ >> 2, pp = pg_ & 3;
        int ll = idx & 31, lt = ll & 3, lg = ll >> 2;
        int r0 = 16 * s + 2 * lt;
        int c0 = 16 * pp + lg;
        uint4 v;
        v.x = pack_h2(W2g[r0 * 64 + c0],       W2g[(r0 + 1) * 64 + c0]);
        v.y = pack_h2(W2g[(r0 + 8) * 64 + c0], W2g[(r0 + 9) * 64 + c0]);
        v.z = pack_h2(W2g[r0 * 64 + c0 + 8],       W2g[(r0 + 1) * 64 + c0 + 8]);
        v.w = pack_h2(W2g[(r0 + 8) * 64 + c0 + 8], W2g[(r0 + 9) * 64 + c0 + 8]);
        *(uint4*)(smem + OFF_W2F + idx * 16) = v;
    }
    if (tid < 128) smf[OFF_B1 / 4 + tid] = b1g[tid];
    if (tid < 64)  smf[OFF_B2 / 4 + tid] = b2g[tid];
    __syncthreads();

    float* stg = smf + OFF_STG / 4;
    const int t0 = blockIdx.x, gstep = gridDim.x;

    // prologue: tile0 thirds -> buf0..2, tile1 third0 -> buf3
    stage_half(stg + 0 * STG_FL, xi, xj, ea, t0 * 192,            tid, nrows); CP_COMMIT();
    stage_half(stg + 1 * STG_FL, xi, xj, ea, t0 * 192 + 64,       tid, nrows); CP_COMMIT();
    stage_half(stg + 2 * STG_FL, xi, xj, ea, t0 * 192 + 128,      tid, nrows); CP_COMMIT();
    stage_half(stg + 3 * STG_FL, xi, xj, ea, (t0 + gstep) * 192,  tid, nrows); CP_COMMIT();

    int q = 0;   // tile's thirds live in bufs q, q+1, q+2 (mod 4)

    for (int tile = t0; tile < ntiles; tile += gstep) {
        CP_WAIT(1);            // this tile's 3 thirds arrived (next tile's h0 may fly)
        __syncthreads();

        // warp's 16-row slab: warps 0-3 -> third0, 4-7 -> third1, 8-11 -> third2
        const float* Xw = stg + ((q + (w >> 2)) & 3) * STG_FL
                        + ((w & 3) * 16 + g) * XSTR;

        // ================= layer 1: 16 rows x 128 cols per warp =================
        float acc1[16][4];
        #pragma unroll
        for (int at = 0; at < 16; ++at)
            #pragma unroll
            for (int r = 0; r < 4; ++r) acc1[at][r] = 0.f;

        #pragma unroll
        for (int s = 0; s < 9; ++s) {
            float2 l0 = *(const float2*)(Xw + 16 * s + t2);                  // row g,   k lo
            float2 l1 = *(const float2*)(Xw + 8 * XSTR + 16 * s + t2);       // row g+8, k lo
            float2 l2 = *(const float2*)(Xw + 16 * s + 8 + t2);              // row g,   k hi
            float2 l3 = *(const float2*)(Xw + 8 * XSTR + 16 * s + 8 + t2);   // row g+8, k hi
            uint32_t a[4];
            a[0] = pack_h2(l0.x, l0.y);
            a[1] = pack_h2(l1.x, l1.y);
            a[2] = pack_h2(l2.x, l2.y);
            a[3] = pack_h2(l3.x, l3.y);
            #pragma unroll
            for (int pp = 0; pp < 8; ++pp) {
                uint4 B = *(const uint4*)(smem + OFF_W1F + ((s * 8 + pp) * 32 + lane) * 16);
                mma_f16(acc1[2 * pp],     a, B.x, B.y);
                mma_f16(acc1[2 * pp + 1], a, B.z, B.w);
            }
        }

        // ---- bias + prelu -> fp16 H fragments IN PLACE (acc1[at][0],[1]) ----
        #pragma unroll
        for (int at = 0; at < 16; ++at) {
            float2 b = *(const float2*)(smf + OFF_B1 / 4 + 8 * at + t2);
            float v0 = acc1[at][0] + b.x;   // row g,   col 8at+2t
            float v1 = acc1[at][1] + b.y;   // row g,   col 8at+2t+1
            float v2 = acc1[at][2] + b.x;   // row g+8, col 8at+2t
            float v3 = acc1[at][3] + b.y;
            v0 = (v0 >= 0.f) ? v0 : alpha * v0;
            v1 = (v1 >= 0.f) ? v1 : alpha * v1;
            v2 = (v2 >= 0.f) ? v2 : alpha * v2;
            v3 = (v3 >= 0.f) ? v3 : alpha * v3;
            acc1[at][0] = __uint_as_float(pack_h2(v0, v1));   // row g pair
            acc1[at][1] = __uint_as_float(pack_h2(v2, v3));   // row g+8 pair
        }
        __syncthreads();       // all X reads of this tile complete

        // ---- prefetch: next tile thirds 1,2 and tile+2 third 0 (freed bufs) ----
        stage_half(stg + ((q + 0) & 3) * STG_FL, xi, xj, ea,
                   (tile + gstep) * 192 + 64,  tid, nrows); CP_COMMIT();
        stage_half(stg + ((q + 1) & 3) * STG_FL, xi, xj, ea,
                   (tile + gstep) * 192 + 128, tid, nrows); CP_COMMIT();
        stage_half(stg + ((q + 2) & 3) * STG_FL, xi, xj, ea,
                   (tile + 2 * gstep) * 192,   tid, nrows); CP_COMMIT();

        // ================= layer 2: H(regs) @ W2 -> 16 rows x 64 cols =================
        float acc2[8][4];
        #pragma unroll
        for (int at = 0; at < 8; ++at)
            #pragma unroll
            for (int r = 0; r < 4; ++r) acc2[at][r] = 0.f;

        #pragma unroll
        for (int s = 0; s < 8; ++s) {
            // k-step s covers H cols 16s..16s+15 = D blocks 2s (k lo) and 2s+1 (k hi)
            uint32_t a[4];
            a[0] = __float_as_uint(acc1[2 * s][0]);       // row g,   k 16s+2t,2t+1
            a[1] = __float_as_uint(acc1[2 * s][1]);       // row g+8
            a[2] = __float_as_uint(acc1[2 * s + 1][0]);   // row g,   k 16s+8+2t
            a[3] = __float_as_uint(acc1[2 * s + 1][1]);   // row g+8
            #pragma unroll
            for (int pp = 0; pp < 4; ++pp) {
                uint4 B = *(const uint4*)(smem + OFF_W2F + ((s * 4 + pp) * 32 + lane) * 16);
                mma_f16(acc2[2 * pp],     a, B.x, B.y);
                mma_f16(acc2[2 * pp + 1], a, B.z, B.w);
            }
        }

        // ---- epilogue 2: bias + prelu -> gmem ----
        int rowbase = tile * 192 + (w << 4) + g;
        #pragma unroll
        for (int at = 0; at < 8; ++at) {
            int col = 8 * at + t2;
            float2 b = *(const float2*)(smf + OFF_B2 / 4 + col);
            float v0 = acc2[at][0] + b.x;
            float v1 = acc2[at][1] + b.y;
            float v2 = acc2[at][2] + b.x;
            float v3 = acc2[at][3] + b.y;
            v0 = (v0 >= 0.f) ? v0 : alpha * v0;
            v1 = (v1 >= 0.f) ? v1 : alpha * v1;
            v2 = (v2 >= 0.f) ? v2 : alpha * v2;
            v3 = (v3 >= 0.f) ? v3 : alpha * v3;
            if (rowbase < nrows)
                *(float2*)(out + (size_t)rowbase * 64 + col) = make_float2(v0, v1);
            if (rowbase + 8 < nrows)
                *(float2*)(out + (size_t)(rowbase + 8) * 64 + col) = make_float2(v2, v3);
        }

        q = (q + 3) & 3;
    }
}

extern "C" void kernel_launch(void* const* d_in, const int* in_sizes, int n_in,
                              void* d_out, int out_size) {
    const float* xi     = (const float*)d_in[0];
    const float* xj     = (const float*)d_in[1];
    const float* ea     = (const float*)d_in[2];
    const float* W1     = (const float*)d_in[3];
    const float* b1     = (const float*)d_in[4];
    const float* W2     = (const float*)d_in[5];
    const float* b2     = (const float*)d_in[6];
    const float* alphap = (const float*)d_in[7];
    float* out = (float*)d_out;

    int nrows  = in_sizes[0] / 64;                 // E*H
    int ntiles = (nrows + 191) / 192;

    int dev = 0, sms = 148;
    cudaGetDevice(&dev);
    cudaDeviceGetAttribute(&sms, cudaDevAttrMultiProcessorCount, dev);

    cudaFuncSetAttribute(message_pass_22548578304895_kernel,
                         cudaFuncAttributeMaxDynamicSharedMemorySize, SMEM_BYTES);

    int grid = sms < ntiles ? sms : ntiles;
    message_pass_22548578304895_kernel<<<grid, 384, SMEM_BYTES>>>(
        xi, xj, ea, W1, b1, W2, b2, alphap, out, nrows, ntiles);
}

// round 17
// speedup vs baseline: 2.7849x; 1.0308x over previous
#include <cuda_runtime.h>
#include <cuda_fp16.h>
#include <cstdint>

// message_pass: out = prelu(prelu([x_i|x_j|ea] @ W1 + b1, a) @ W2 + b2, a)
// E*H=500000 rows, d_in=144, HID=128, C=64. fp32 I/O, FP16 mma (m16n8k16, fp32 acc).
// 256 threads / 8 warps; warp w owns 32 rows (two m16 slabs) of a 256-row tile,
// all columns of both layers -> each B-fragment LDS.128 feeds 4 mmas.
// Layer-1 accumulators convert in place to layer-2 A fragments (H stays in regs).
// X staged via cp.async into 4 fixed 64-row buffers (one full tile), next tile
// prefetched after the post-layer1 barrier, overlapping layer 2.

#define XSTR 152                          // staging row stride (floats): conflict-free LDS.64
#define OFF_W1F 0                         // 36864 B : W1 pair-packed fragments (9 steps x 8 pairs)
#define OFF_W2F 36864                     // 16384 B : W2 pair-packed fragments (8 steps x 4 pairs)
#define OFF_STG 53248                     // 4 x 64-row staging buffers (= one 256-row tile)
#define STG_FL  (64*XSTR)                 // floats per buffer
#define STG_BY  (STG_FL*4)                // 38912 B each
#define OFF_B1  (OFF_STG + 4*STG_BY)      // 208896
#define OFF_B2  (OFF_B1 + 512)            // 209408
#define SMEM_BYTES (OFF_B2 + 256)         // 209664 B

__device__ __forceinline__ uint32_t pack_h2(float lo, float hi) {
    __half2 h = __floats2half2_rn(lo, hi);
    return *reinterpret_cast<uint32_t*>(&h);
}

__device__ __forceinline__ void mma_f16(float* d, const uint32_t* a,
                                        uint32_t b0, uint32_t b1) {
    asm volatile(
        "mma.sync.aligned.m16n8k16.row.col.f32.f16.f16.f32 "
        "{%0,%1,%2,%3}, {%4,%5,%6,%7}, {%8,%9}, {%0,%1,%2,%3};"
        : "+f"(d[0]), "+f"(d[1]), "+f"(d[2]), "+f"(d[3])
        : "r"(a[0]), "r"(a[1]), "r"(a[2]), "r"(a[3]), "r"(b0), "r"(b1));
}

__device__ __forceinline__ void cp_async16(float* smem_dst, const float* gsrc, int src_bytes) {
    uint32_t sa = (uint32_t)__cvta_generic_to_shared(smem_dst);
    asm volatile("cp.async.cg.shared.global [%0], [%1], 16, %2;"
                 :: "r"(sa), "l"(gsrc), "r"(src_bytes));
}
#define CP_COMMIT() asm volatile("cp.async.commit_group;" ::: "memory")
#define CP_WAIT(n)  asm volatile("cp.async.wait_group %0;" :: "n"(n) : "memory")

// stage 64 rows (grow0..grow0+63) of [x_i|x_j|ea] into dst (stride XSTR)
__device__ __forceinline__ void stage_quarter(
    float* dst, const float* __restrict__ xi, const float* __restrict__ xj,
    const float* __restrict__ ea, int grow0, int tid, int nrows)
{
    #pragma unroll
    for (int j = 0; j < 9; ++j) {
        int v   = tid + 256 * j;          // 2304 = 64 rows * 36 float4
        int row = v / 36;
        int col = (v % 36) * 4;
        int grow = grow0 + row;
        int nb   = (grow < nrows) ? 16 : 0;
        int gr   = (grow < nrows) ? grow : (nrows - 1);
        const float* src;
        if (col < 64)        src = xi + (size_t)gr * 64 + col;
        else if (col < 128)  src = xj + (size_t)gr * 64 + (col - 64);
        else                 src = ea + (size_t)gr * 16 + (col - 128);
        cp_async16(dst + row * XSTR + col, src, nb);
    }
}

__global__ __launch_bounds__(256, 1)
void message_pass_22548578304895_kernel(
    const float* __restrict__ xi, const float* __restrict__ xj,
    const float* __restrict__ ea, const float* __restrict__ W1g,
    const float* __restrict__ b1g, const float* __restrict__ W2g,
    const float* __restrict__ b2g, const float* __restrict__ alphap,
    float* __restrict__ out, int nrows, int ntiles)
{
    extern __shared__ char smem[];
    float* smf = (float*)smem;
    const int tid  = threadIdx.x;
    const int w    = tid >> 5;
    const int lane = tid & 31;
    const int g    = lane >> 2;
    const int t    = lane & 3;
    const int t2   = 2 * t;
    const float alpha = __ldg(alphap);

    // ---- pack W1 fragments (m16n8k16 B layout, col-pairs):
    //      entry (s,pp), lane(lt,lg), c0 = 16pp+lg:
    //      .x = h2(W[16s+2lt][c0],   W[16s+2lt+1][c0])   b0 of block 2pp
    //      .y = h2(W[16s+2lt+8][c0], W[16s+2lt+9][c0])   b1 of block 2pp
    //      .z/.w = same for c0+8 (block 2pp+1)
    for (int idx = tid; idx < 2304; idx += 256) {
        int pg_ = idx >> 5;
        int s = pg_ >> 3, pp = pg_ & 7;
        int ll = idx & 31, lt = ll & 3, lg = ll >> 2;
        int r0 = 16 * s + 2 * lt;
        int c0 = 16 * pp + lg;
        uint4 v;
        v.x = pack_h2(W1g[r0 * 128 + c0],       W1g[(r0 + 1) * 128 + c0]);
        v.y = pack_h2(W1g[(r0 + 8) * 128 + c0], W1g[(r0 + 9) * 128 + c0]);
        v.z = pack_h2(W1g[r0 * 128 + c0 + 8],       W1g[(r0 + 1) * 128 + c0 + 8]);
        v.w = pack_h2(W1g[(r0 + 8) * 128 + c0 + 8], W1g[(r0 + 9) * 128 + c0 + 8]);
        *(uint4*)(smem + OFF_W1F + idx * 16) = v;
    }
    for (int idx = tid; idx < 1024; idx += 256) {
        int pg_ = idx >> 5;
        int s = pg_ >> 2, pp = pg_ & 3;
        int ll = idx & 31, lt = ll & 3, lg = ll >> 2;
        int r0 = 16 * s + 2 * lt;
        int c0 = 16 * pp + lg;
        uint4 v;
        v.x = pack_h2(W2g[r0 * 64 + c0],       W2g[(r0 + 1) * 64 + c0]);
        v.y = pack_h2(W2g[(r0 + 8) * 64 + c0], W2g[(r0 + 9) * 64 + c0]);
        v.z = pack_h2(W2g[r0 * 64 + c0 + 8],       W2g[(r0 + 1) * 64 + c0 + 8]);
        v.w = pack_h2(W2g[(r0 + 8) * 64 + c0 + 8], W2g[(r0 + 9) * 64 + c0 + 8]);
        *(uint4*)(smem + OFF_W2F + idx * 16) = v;
    }
    if (tid < 128) smf[OFF_B1 / 4 + tid] = b1g[tid];
    if (tid < 64)  smf[OFF_B2 / 4 + tid] = b2g[tid];
    __syncthreads();

    float* stg = smf + OFF_STG / 4;
    const int t0 = blockIdx.x, gstep = gridDim.x;

    // prologue: all 4 quarters of first tile
    #pragma unroll
    for (int i = 0; i < 4; ++i) {
        stage_quarter(stg + i * STG_FL, xi, xj, ea, t0 * 256 + 64 * i, tid, nrows);
        CP_COMMIT();
    }

    for (int tile = t0; tile < ntiles; tile += gstep) {
        CP_WAIT(0);            // whole tile staged
        __syncthreads();

        // warp w owns rows 32w..32w+31: buffer w>>1, row offset (w&1)*32
        const float* Xw = stg + (w >> 1) * STG_FL + ((w & 1) * 32 + g) * XSTR;

        // ================= layer 1: 32 rows x 128 cols per warp =================
        float acc1[2][16][4];
        #pragma unroll
        for (int f = 0; f < 2; ++f)
            #pragma unroll
            for (int at = 0; at < 16; ++at)
                #pragma unroll
                for (int r = 0; r < 4; ++r) acc1[f][at][r] = 0.f;

        #pragma unroll
        for (int s = 0; s < 9; ++s) {
            uint32_t a[2][4];
            #pragma unroll
            for (int f = 0; f < 2; ++f) {
                const float* Xs = Xw + f * 16 * XSTR + 16 * s;
                float2 l0 = *(const float2*)(Xs + t2);                  // row g,   k lo
                float2 l1 = *(const float2*)(Xs + 8 * XSTR + t2);       // row g+8, k lo
                float2 l2 = *(const float2*)(Xs + 8 + t2);              // row g,   k hi
                float2 l3 = *(const float2*)(Xs + 8 * XSTR + 8 + t2);   // row g+8, k hi
                a[f][0] = pack_h2(l0.x, l0.y);
                a[f][1] = pack_h2(l1.x, l1.y);
                a[f][2] = pack_h2(l2.x, l2.y);
                a[f][3] = pack_h2(l3.x, l3.y);
            }
            #pragma unroll
            for (int pp = 0; pp < 8; ++pp) {
                uint4 B = *(const uint4*)(smem + OFF_W1F + ((s * 8 + pp) * 32 + lane) * 16);
                #pragma unroll
                for (int f = 0; f < 2; ++f) {
                    mma_f16(acc1[f][2 * pp],     a[f], B.x, B.y);
                    mma_f16(acc1[f][2 * pp + 1], a[f], B.z, B.w);
                }
            }
        }

        // ---- bias + prelu -> fp16 H fragments IN PLACE (acc1[f][at][0],[1]) ----
        #pragma unroll
        for (int f = 0; f < 2; ++f) {
            #pragma unroll
            for (int at = 0; at < 16; ++at) {
                float2 b = *(const float2*)(smf + OFF_B1 / 4 + 8 * at + t2);
                float v0 = acc1[f][at][0] + b.x;   // row g,   col 8at+2t
                float v1 = acc1[f][at][1] + b.y;   // row g,   col 8at+2t+1
                float v2 = acc1[f][at][2] + b.x;   // row g+8, col 8at+2t
                float v3 = acc1[f][at][3] + b.y;
                v0 = (v0 >= 0.f) ? v0 : alpha * v0;
                v1 = (v1 >= 0.f) ? v1 : alpha * v1;
                v2 = (v2 >= 0.f) ? v2 : alpha * v2;
                v3 = (v3 >= 0.f) ? v3 : alpha * v3;
                acc1[f][at][0] = __uint_as_float(pack_h2(v0, v1));   // row g pair
                acc1[f][at][1] = __uint_as_float(pack_h2(v2, v3));   // row g+8 pair
            }
        }
        __syncthreads();       // all X reads of this tile complete

        // ---- prefetch all 4 quarters of the next tile (overlaps layer 2) ----
        {
            int nt = tile + gstep;
            int base = ((nt < ntiles) ? nt : tile) * 256;
            #pragma unroll
            for (int i = 0; i < 4; ++i) {
                stage_quarter(stg + i * STG_FL, xi, xj, ea, base + 64 * i, tid, nrows);
                CP_COMMIT();
            }
        }

        // ================= layer 2: H(regs) @ W2 -> 32 rows x 64 cols =================
        float acc2[2][8][4];
        #pragma unroll
        for (int f = 0; f < 2; ++f)
            #pragma unroll
            for (int at = 0; at < 8; ++at)
                #pragma unroll
                for (int r = 0; r < 4; ++r) acc2[f][at][r] = 0.f;

        #pragma unroll
        for (int s = 0; s < 8; ++s) {
            // k-step s covers H cols 16s..16s+15 = D blocks 2s (k lo) and 2s+1 (k hi)
            uint32_t a[2][4];
            #pragma unroll
            for (int f = 0; f < 2; ++f) {
                a[f][0] = __float_as_uint(acc1[f][2 * s][0]);       // row g,   k 16s+2t
                a[f][1] = __float_as_uint(acc1[f][2 * s][1]);       // row g+8
                a[f][2] = __float_as_uint(acc1[f][2 * s + 1][0]);   // row g,   k 16s+8+2t
                a[f][3] = __float_as_uint(acc1[f][2 * s + 1][1]);   // row g+8
            }
            #pragma unroll
            for (int pp = 0; pp < 4; ++pp) {
                uint4 B = *(const uint4*)(smem + OFF_W2F + ((s * 4 + pp) * 32 + lane) * 16);
                #pragma unroll
                for (int f = 0; f < 2; ++f) {
                    mma_f16(acc2[f][2 * pp],     a[f], B.x, B.y);
                    mma_f16(acc2[f][2 * pp + 1], a[f], B.z, B.w);
                }
            }
        }

        // ---- epilogue 2: bias + prelu -> gmem ----
        #pragma unroll
        for (int f = 0; f < 2; ++f) {
            int rowbase = tile * 256 + (w << 5) + f * 16 + g;
            #pragma unroll
            for (int at = 0; at < 8; ++at) {
                int col = 8 * at + t2;
                float2 b = *(const float2*)(smf + OFF_B2 / 4 + col);
                float v0 = acc2[f][at][0] + b.x;
                float v1 = acc2[f][at][1] + b.y;
                float v2 = acc2[f][at][2] + b.x;
                float v3 = acc2[f][at][3] + b.y;
                v0 = (v0 >= 0.f) ? v0 : alpha * v0;
                v1 = (v1 >= 0.f) ? v1 : alpha * v1;
                v2 = (v2 >= 0.f) ? v2 : alpha * v2;
                v3 = (v3 >= 0.f) ? v3 : alpha * v3;
                if (rowbase < nrows)
                    *(float2*)(out + (size_t)rowbase * 64 + col) = make_float2(v0, v1);
                if (rowbase + 8 < nrows)
                    *(float2*)(out + (size_t)(rowbase + 8) * 64 + col) = make_float2(v2, v3);
            }
        }
    }
}

extern "C" void kernel_launch(void* const* d_in, const int* in_sizes, int n_in,
                              void* d_out, int out_size) {
    const float* xi     = (const float*)d_in[0];
    const float* xj     = (const float*)d_in[1];
    const float* ea     = (const float*)d_in[2];
    const float* W1     = (const float*)d_in[3];
    const float* b1     = (const float*)d_in[4];
    const float* W2     = (const float*)d_in[5];
    const float* b2     = (const float*)d_in[6];
    const float* alphap = (const float*)d_in[7];
    float* out = (float*)d_out;

    int nrows  = in_sizes[0] / 64;                 // E*H
    int ntiles = (nrows + 255) / 256;

    int dev = 0, sms = 148;
    cudaGetDevice(&dev);
    cudaDeviceGetAttribute(&sms, cudaDevAttrMultiProcessorCount, dev);

    cudaFuncSetAttribute(message_pass_22548578304895_kernel,
                         cudaFuncAttributeMaxDynamicSharedMemorySize, SMEM_BYTES);

    int grid = sms < ntiles ? sms : ntiles;
    message_pass_22548578304895_kernel<<<grid, 256, SMEM_BYTES>>>(
        xi, xj, ea, W1, b1, W2, b2, alphap, out, nrows, ntiles);
}